// round 12
// baseline (speedup 1.0000x reference)
#include <cuda_runtime.h>

#define NNODES 50000
#define DD 16
#define BB 32
#define NDRVN 500
#define FEAT 5
#define NMID 5

// State buffers
__device__ float g_zA[NNODES * BB];
__device__ float g_zB[NNODES * BB];
__device__ float g_z3[NDRVN * DD * BB];
__device__ float g_zf[NDRVN * BB];
__device__ unsigned char g_need[NNODES];   // nodes whose z2 is consumed by pass3

// Weights in constant memory (filled by async D2D copies in kernel_launch)
__constant__ float c_wf[FEAT * 3];
__constant__ float c_bf[FEAT];
__constant__ float c_wm[NMID * FEAT * FEAT * 3];
__constant__ float c_bm[NMID * FEAT];
__constant__ float c_wl[FEAT * 3];
__constant__ float c_bl[1];

// ---------------------------------------------------------------------------
// Transpose x [B, N] -> g_zA [N, B]
// ---------------------------------------------------------------------------
__global__ void transpose_kernel(const float* __restrict__ x) {
    __shared__ float tile[32][33];
    int n0 = blockIdx.x * 32;
    int tx = threadIdx.x, ty = threadIdx.y;
    int n = n0 + tx;
    if (n < NNODES) tile[ty][tx] = x[ty * NNODES + n];
    __syncthreads();
    int n2 = n0 + ty;
    if (n2 < NNODES) g_zA[n2 * BB + tx] = tile[tx][ty];
}

// ---------------------------------------------------------------------------
// Mark nodes needed from pass 2: nbr(nbr(drivers)).  Idempotent (writes 1s),
// so replays are deterministic without re-zeroing.
// ---------------------------------------------------------------------------
__global__ void mark_kernel(const int* __restrict__ nbr,
                            const int* __restrict__ drivers) {
    unsigned tid = blockIdx.x * blockDim.x + threadIdx.x;
    if (tid >= (unsigned)NDRVN * DD * DD) return;
    int d = tid >> 8;           // driver index
    int j = (tid >> 4) & 15;    // first-hop slot
    int k = tid & 15;           // second-hop slot
    int m = __ldg(&nbr[__ldg(&drivers[d]) * DD + j]);
    int node = __ldg(&nbr[m * DD + k]);
    g_need[node] = 1;
}

// ===========================================================================
// Constant-weight conv stack (proven fastest body, R10/R11)
// ===========================================================================
template <int WIN, int AW, int BW>
__device__ __forceinline__ void mid_layer_c(const float (&hin)[FEAT][AW],
                                            float (&hout)[FEAT][BW],
                                            int L) {
    const float* wbase = c_wm + L * FEAT * FEAT * 3;
    const float* bbase = c_bm + L * FEAT;
    #pragma unroll
    for (int co = 0; co < FEAT; co++) {
        float bias = bbase[co];
        #pragma unroll
        for (int w = 0; w < WIN - 2; w++) {
            float a = bias;
            #pragma unroll
            for (int ci = 0; ci < FEAT; ci++) {
                a = fmaf(wbase[(co * FEAT + ci) * 3 + 0], hin[ci][w + 0], a);
                a = fmaf(wbase[(co * FEAT + ci) * 3 + 1], hin[ci][w + 1], a);
                a = fmaf(wbase[(co * FEAT + ci) * 3 + 2], hin[ci][w + 2], a);
            }
            hout[co][w] = fmaxf(a, 0.0f);
        }
    }
}

__device__ __forceinline__ float conv_stack_c(const float (&v)[DD]) {
    float hA[FEAT][14];
    #pragma unroll
    for (int c = 0; c < FEAT; c++) {
        float bias = c_bf[c];
        #pragma unroll
        for (int w = 0; w < 14; w++) {
            float a = bias;
            a = fmaf(c_wf[c * 3 + 0], v[w + 0], a);
            a = fmaf(c_wf[c * 3 + 1], v[w + 1], a);
            a = fmaf(c_wf[c * 3 + 2], v[w + 2], a);
            hA[c][w] = fmaxf(a, 0.0f);
        }
    }

    float hB[FEAT][12];
    mid_layer_c<14>(hA, hB, 0);
    mid_layer_c<12>(hB, hA, 1);
    mid_layer_c<10>(hA, hB, 2);
    mid_layer_c<8>(hB, hA, 3);
    mid_layer_c<6>(hA, hB, 4);

    float o[2];
    #pragma unroll
    for (int w = 0; w < 2; w++) {
        float a = c_bl[0];
        #pragma unroll
        for (int ci = 0; ci < FEAT; ci++) {
            a = fmaf(c_wl[ci * 3 + 0], hB[ci][w + 0], a);
            a = fmaf(c_wl[ci * 3 + 1], hB[ci][w + 1], a);
            a = fmaf(c_wl[ci * 3 + 2], hB[ci][w + 2], a);
        }
        o[w] = fmaxf(a, 0.0f);
    }
    return 0.5f * (o[0] + o[1]);
}

// ---------------------------------------------------------------------------
// Pass 1 (full): zA -> zB, all nodes.  warp = node, lane = batch
// ---------------------------------------------------------------------------
__global__ void __launch_bounds__(128)
pass1_full(const int* __restrict__ nbr) {
    unsigned gid = blockIdx.x * blockDim.x + threadIdx.x;
    int n = gid >> 5;
    int b = gid & 31;

    float v[DD];
    const int* nb = nbr + n * DD;
    #pragma unroll
    for (int d = 0; d < DD; d++) {
        int idx = __ldg(&nb[d]);
        v[d] = __ldg(&g_zA[idx * BB + b]);
    }
    g_zB[n * BB + b] = conv_stack_c(v);
}

// ---------------------------------------------------------------------------
// Pass 2 (pruned): zB -> zA, only nodes in g_need (~92%).  Warp-uniform exit.
// ---------------------------------------------------------------------------
__global__ void __launch_bounds__(128)
pass2_pruned(const int* __restrict__ nbr) {
    unsigned gid = blockIdx.x * blockDim.x + threadIdx.x;
    int n = gid >> 5;
    int b = gid & 31;

    if (!__ldg(&g_need[n])) return;   // warp-uniform: whole warp exits

    float v[DD];
    const int* nb = nbr + n * DD;
    #pragma unroll
    for (int d = 0; d < DD; d++) {
        int idx = __ldg(&nb[d]);
        v[d] = __ldg(&g_zB[idx * BB + b]);
    }
    g_zA[n * BB + b] = conv_stack_c(v);
}

// ---------------------------------------------------------------------------
// Pass 3 (lite): z3 at the 500x16 driver-neighbor slots, reads g_zA (z2)
// ---------------------------------------------------------------------------
__global__ void __launch_bounds__(128)
pass3_lite(const int* __restrict__ nbr, const int* __restrict__ drivers) {
    unsigned gid = blockIdx.x * blockDim.x + threadIdx.x;
    if (gid >= (unsigned)NDRVN * DD * BB) return;
    int job = gid >> 5;
    int b = gid & 31;

    int d = job >> 4;
    int j = job & 15;
    int m = __ldg(&nbr[__ldg(&drivers[d]) * DD + j]);

    float v[DD];
    const int* nb = nbr + m * DD;
    #pragma unroll
    for (int k = 0; k < DD; k++) {
        int idx = __ldg(&nb[k]);
        v[k] = __ldg(&g_zA[idx * BB + b]);
    }
    g_z3[job * BB + b] = conv_stack_c(v);
}

// ---------------------------------------------------------------------------
// Pass 4 (lite): only the 500 driver nodes, inputs direct from g_z3
// ---------------------------------------------------------------------------
__global__ void __launch_bounds__(128)
pass4_lite() {
    unsigned gid = blockIdx.x * blockDim.x + threadIdx.x;
    if (gid >= (unsigned)NDRVN * BB) return;
    int d = gid >> 5;
    int b = gid & 31;

    float v[DD];
    #pragma unroll
    for (int k = 0; k < DD; k++)
        v[k] = __ldg(&g_z3[(d * DD + k) * BB + b]);
    g_zf[d * BB + b] = conv_stack_c(v);
}

// ---------------------------------------------------------------------------
__global__ void zero_kernel(float4* __restrict__ out, int n4) {
    int i = blockIdx.x * blockDim.x + threadIdx.x;
    if (i < n4) out[i] = make_float4(0.f, 0.f, 0.f, 0.f);
}

// ---------------------------------------------------------------------------
// Masked softmax over driver columns; reads g_zf [500][B]
// ---------------------------------------------------------------------------
__global__ void softmax_kernel(const int* __restrict__ drivers,
                               float* __restrict__ out) {
    __shared__ float red[512];
    int b = blockIdx.x;
    int t = threadIdx.x;

    float myv = 0.0f;
    int drv = -1;
    float mval = -INFINITY;
    if (t < NDRVN) {
        drv = drivers[t];
        myv = g_zf[t * BB + b];
        mval = myv;
    }
    red[t] = mval;
    __syncthreads();
    #pragma unroll
    for (int s = 256; s > 0; s >>= 1) {
        if (t < s) red[t] = fmaxf(red[t], red[t + s]);
        __syncthreads();
    }
    float m = fmaxf(red[0], 0.0f);
    __syncthreads();

    float e = (t < NDRVN) ? expf(myv - m) : 0.0f;
    red[t] = e;
    __syncthreads();
    #pragma unroll
    for (int s = 256; s > 0; s >>= 1) {
        if (t < s) red[t] += red[t + s];
        __syncthreads();
    }
    float Z = red[0] + (float)(NNODES - NDRVN) * expf(-m);

    if (t < NDRVN) out[b * NNODES + drv] = e / Z;
}

// ---------------------------------------------------------------------------
extern "C" void kernel_launch(void* const* d_in, const int* in_sizes, int n_in,
                              void* d_out, int out_size) {
    const float* x       = (const float*)d_in[0];
    const int*   nbr     = (const int*)  d_in[1];
    const int*   drivers = (const int*)  d_in[2];
    const float* w_first = (const float*)d_in[4];
    const float* b_first = (const float*)d_in[5];
    const float* w_mid   = (const float*)d_in[6];
    const float* b_mid   = (const float*)d_in[7];
    const float* w_last  = (const float*)d_in[8];
    const float* b_last  = (const float*)d_in[9];
    float* out = (float*)d_out;

    // Copy weights into __constant__ (graph-capturable D2D memcpy nodes)
    cudaMemcpyToSymbolAsync(c_wf, w_first, FEAT * 3 * sizeof(float), 0, cudaMemcpyDeviceToDevice);
    cudaMemcpyToSymbolAsync(c_bf, b_first, FEAT * sizeof(float), 0, cudaMemcpyDeviceToDevice);
    cudaMemcpyToSymbolAsync(c_wm, w_mid, NMID * FEAT * FEAT * 3 * sizeof(float), 0, cudaMemcpyDeviceToDevice);
    cudaMemcpyToSymbolAsync(c_bm, b_mid, NMID * FEAT * sizeof(float), 0, cudaMemcpyDeviceToDevice);
    cudaMemcpyToSymbolAsync(c_wl, w_last, FEAT * 3 * sizeof(float), 0, cudaMemcpyDeviceToDevice);
    cudaMemcpyToSymbolAsync(c_bl, b_last, sizeof(float), 0, cudaMemcpyDeviceToDevice);

    // Independent prologue work
    int n4 = NNODES * BB / 4;
    zero_kernel<<<(n4 + 255) / 256, 256>>>((float4*)out, n4);
    mark_kernel<<<(NDRVN * DD * DD + 255) / 256, 256>>>(nbr, drivers);
    transpose_kernel<<<(NNODES + 31) / 32, dim3(32, 32)>>>(x);

    const int blk = 128;
    const int grid_sc = (NNODES * BB + blk - 1) / blk;

    pass1_full<<<grid_sc, blk>>>(nbr);       // zA -> zB (all nodes)
    pass2_pruned<<<grid_sc, blk>>>(nbr);     // zB -> zA (marked nodes only)

    const int grid3 = (NDRVN * DD * BB + blk - 1) / blk;
    pass3_lite<<<grid3, blk>>>(nbr, drivers);

    const int grid4 = (NDRVN * BB + blk - 1) / blk;
    pass4_lite<<<grid4, blk>>>();

    softmax_kernel<<<BB, 512>>>(drivers, out);
}